// round 14
// baseline (speedup 1.0000x reference)
#include <cuda_runtime.h>
#include <cuda_bf16.h>
#include <cstdint>

#define K_CODES 8192
#define CDIM    256
#define SPAT    4096
#define NROWS   32768
#define OUT_ELEMS (8 * CDIM * SPAT)

#define ROWS_CTA 64
#define PANEL    64                    // codes per tile
#define T_TILES  (K_CODES / PANEL)     // 128
#define A_SPLIT  32768                 // 64 rows * 512 B (staging, split stride)
#define BP_SPLIT 32768                 // 64 codes * 512 B per split
#define PBLK     65792                 // packed block: 2*32768 + 256 cbn
#define BSTRIDE  66048                 // smem buffer stride (512-mult)
#define SMEM_TOTAL (3 * BSTRIDE)       // 198144 B

typedef unsigned long long ull;

// ---- scratch ----
__device__ uint4  g_c0[K_CODES * CDIM / 8];   // bf16 splits, [code][k] contiguous
__device__ uint4  g_c1[K_CODES * CDIM / 8];
__device__ uint4  g_pack[T_TILES * (PBLK / 16)];  // pre-swizzled panels + cbn
__device__ float  g_cbn[K_CODES];
__device__ float  g_zn[NROWS];
__device__ int    g_cand[NROWS * 16];
__device__ int    g_idx[NROWS];
__device__ double g_loss;

// ---------------- PTX helpers ----------------
__device__ __forceinline__ uint32_t smem_u32(const void* p) {
    uint32_t a;
    asm("{ .reg .u64 t; cvta.to.shared.u64 t, %1; cvt.u32.u64 %0, t; }" : "=r"(a) : "l"(p));
    return a;
}
#define CP16(dst, src) asm volatile("cp.async.cg.shared.global [%0], [%1], 16;" :: "r"(dst), "l"(src))
#define CP_COMMIT()    asm volatile("cp.async.commit_group;" ::: "memory")
#define CP_WAIT0()     asm volatile("cp.async.wait_group 0;" ::: "memory")
#define CP_WAIT1()     asm volatile("cp.async.wait_group 1;" ::: "memory")

__device__ __forceinline__ void ldsm4(uint32_t& r0, uint32_t& r1, uint32_t& r2, uint32_t& r3,
                                      uint32_t addr) {
    asm volatile("ldmatrix.sync.aligned.m8n8.x4.shared.b16 {%0,%1,%2,%3}, [%4];"
                 : "=r"(r0), "=r"(r1), "=r"(r2), "=r"(r3) : "r"(addr));
}
__device__ __forceinline__ void mma_bf16(float* c, uint32_t a0, uint32_t a1, uint32_t a2,
                                         uint32_t a3, uint32_t b0, uint32_t b1) {
    asm volatile(
        "mma.sync.aligned.m16n8k16.row.col.f32.bf16.bf16.f32 "
        "{%0,%1,%2,%3}, {%4,%5,%6,%7}, {%8,%9}, {%0,%1,%2,%3};"
        : "+f"(c[0]), "+f"(c[1]), "+f"(c[2]), "+f"(c[3])
        : "r"(a0), "r"(a1), "r"(a2), "r"(a3), "r"(b0), "r"(b1));
}

// ---------------- K1: codebook 2-way split + norms ----------------
__global__ void k_cbprep(const float* __restrict__ cb) {
    int k = blockIdx.x, c = threadIdx.x;
    float v = cb[k * CDIM + c];
    __nv_bfloat16 c0 = __float2bfloat16_rn(v);
    float r1 = v - __bfloat162float(c0);
    __nv_bfloat16 c1 = __float2bfloat16_rn(r1);
    ((__nv_bfloat16*)g_c0)[k * CDIM + c] = c0;
    ((__nv_bfloat16*)g_c1)[k * CDIM + c] = c1;
    float s = v * v;
    #pragma unroll
    for (int o = 16; o > 0; o >>= 1) s += __shfl_xor_sync(~0u, s, o);
    __shared__ float ws[8];
    if ((c & 31) == 0) ws[c >> 5] = s;
    __syncthreads();
    if (c == 0) {
        float t = 0.f;
        #pragma unroll
        for (int i = 0; i < 8; i++) t += ws[i];
        g_cbn[k] = t;
    }
}

// ---------------- K1b: pack panels pre-swizzled (+ cbn slice) ----------------
__global__ void k_pack() {
    int t = blockIdx.x;
    uint4* dst = g_pack + (size_t)t * (PBLK / 16);
    for (int id = threadIdx.x; id < 4096; id += 256) {
        int sp = id >> 11;
        int within = id & 2047;              // 16B chunk within 32KB split
        int code = within >> 5;
        int kcs = (within & 31) << 4;        // swizzled byte pos within 512B row
        int kc = kcs ^ ((code & 7) << 4);    // source byte pos (XOR self-inverse)
        const uint4* srcb = sp ? g_c1 : g_c0;
        dst[id] = srcb[((size_t)(t * PANEL + code) * 512 + kc) >> 4];
    }
    if (threadIdx.x < PANEL)
        ((float*)(dst + 4096))[threadIdx.x] = g_cbn[t * PANEL + threadIdx.x];
}

// ---------------- K2: z row norms ----------------
__global__ void k_zn(const float* __restrict__ z) {
    int n = blockIdx.x * 256 + threadIdx.x;
    int b = n >> 12, p = n & 4095;
    const float* zp = z + (size_t)b * CDIM * SPAT + p;
    float s = 0.f;
    #pragma unroll 8
    for (int c = 0; c < CDIM; c++) {
        float v = zp[(size_t)c * SPAT];
        s = fmaf(v, v, s);
    }
    g_zn[n] = s;
}

__global__ void k_zero() { g_loss = 0.0; }

// ---- issue one packed panel: linear copy, trivial addressing ----
__device__ __forceinline__ void issue_panel(int t, uint32_t dstB, int tid) {
    const char* src = (const char*)g_pack + (size_t)t * PBLK + tid * 16;
    uint32_t d = dstB + tid * 16;
    #pragma unroll
    for (int j = 0; j < 16; j++)
        CP16(d + j * 4096, src + j * 4096);
    if (tid < 16)
        CP16(dstB + 65536 + tid * 16, src - tid * 16 + 65536 + tid * 16);
}

#define UPD(dv, col, d1, k1, d2, k2) \
    do { if ((dv) < (d1)) { d2 = d1; k2 = k1; d1 = (dv); k1 = (col); } \
         else if ((dv) < (d2)) { d2 = (dv); k2 = (col); } } while (0)

// ---------------- K3: HMMA GEMM, A in registers, 3-buffer pipeline ----------
__global__ void __launch_bounds__(256, 1)
k_argmin(const float* __restrict__ z) {
    extern __shared__ char smem[];
    uint32_t sb = smem_u32(smem);
    int tid = threadIdx.x, w = tid >> 5, lane = tid & 31;
    int n0 = blockIdx.x * ROWS_CTA;
    int b = n0 >> 12, p0 = n0 & 4095;

    // ---- stage A (2-split, swizzled) at smem base ----
    {
        int row = tid & 63, kg = tid >> 6;
        const float* zp = z + ((size_t)b * CDIM + kg * 64) * SPAT + p0 + row;
        uint32_t sw = (uint32_t)(row & 7) << 4;
        char* ab = smem + row * 512;
        #pragma unroll 4
        for (int kk = 0; kk < 64; kk += 2) {
            float v0 = zp[(size_t)kk * SPAT];
            float v1 = zp[(size_t)(kk + 1) * SPAT];
            __nv_bfloat16 a0 = __float2bfloat16_rn(v0);
            float ra = v0 - __bfloat162float(a0);
            __nv_bfloat16 a1 = __float2bfloat16_rn(ra);
            __nv_bfloat16 c0 = __float2bfloat16_rn(v1);
            float rc = v1 - __bfloat162float(c0);
            __nv_bfloat16 c1 = __float2bfloat16_rn(rc);
            uint32_t off = (uint32_t)((kg * 64 + kk) * 2) ^ sw;
            *(uint32_t*)(ab + off) =
                (uint32_t)__bfloat16_as_ushort(a0) | ((uint32_t)__bfloat16_as_ushort(c0) << 16);
            *(uint32_t*)(ab + A_SPLIT + off) =
                (uint32_t)__bfloat16_as_ushort(a1) | ((uint32_t)__bfloat16_as_ushort(c1) << 16);
        }
    }
    __syncthreads();

    // ---- A fragments into registers (2 splits x 16 ksteps x 4) ----
    int rowAf = 16 * (w & 3) + (lane & 7) + ((lane >> 3) & 1) * 8;
    uint32_t aOff = (uint32_t)rowAf * 512;
    uint32_t swA = (uint32_t)(rowAf & 7) << 4;
    uint32_t kadd = (uint32_t)(lane >> 4) * 16;
    uint32_t azf[2][16][4];
    #pragma unroll
    for (int s = 0; s < 2; s++)
        #pragma unroll
        for (int ks = 0; ks < 16; ks++)
            ldsm4(azf[s][ks][0], azf[s][ks][1], azf[s][ks][2], azf[s][ks][3],
                  sb + s * A_SPLIT + aOff + (((uint32_t)(ks * 32) + kadd) ^ swA));
    __syncthreads();

    // ---- preload panels 0 and 1 ----
    issue_panel(0, sb, tid);
    CP_COMMIT();
    issue_panel(1, sb + BSTRIDE, tid);
    CP_COMMIT();

    int half = w >> 2;
    int rowBf = 32 * half + (lane & 7) + ((lane >> 3) & 1) * 8;
    uint32_t bOff1 = (uint32_t)rowBf * 512;
    uint32_t bOff2 = bOff1 + 16 * 512;
    uint32_t swB = (uint32_t)(rowBf & 7) << 4;

    int rA = 16 * (w & 3) + (lane >> 2);
    float ZA = g_zn[n0 + rA], ZB = g_zn[n0 + rA + 8];
    float dA1 = 3.4e38f, dA2 = 3.4e38f, dB1 = 3.4e38f, dB2 = 3.4e38f;
    int   kA1 = 0, kA2 = 0, kB1 = 0, kB2 = 0;

    float acc[4][4];
    #pragma unroll
    for (int i = 0; i < 4; i++)
        #pragma unroll
        for (int j = 0; j < 4; j++) acc[i][j] = 0.f;

    #pragma unroll 1
    for (int t = 0; t < T_TILES; t++) {
        int buf = t % 3;
        if (t == T_TILES - 1) { CP_WAIT0(); } else { CP_WAIT1(); }
        __syncthreads();
        if (t + 2 < T_TILES) {
            issue_panel(t + 2, sb + ((t + 2) % 3) * BSTRIDE, tid);
            CP_COMMIT();
        }
        uint32_t Bb = sb + buf * BSTRIDE;

        // passes: (z0,c0), (z0,c1), (z1,c0)
        #pragma unroll
        for (int p = 0; p < 3; p++) {
            const int sa = (p >> 1);
            const int scb = (p & 1);
            uint32_t bSp = Bb + scb * BP_SPLIT;
            #pragma unroll
            for (int ks = 0; ks < 16; ks++) {
                uint32_t colB = ((uint32_t)(ks * 32) + kadd) ^ swB;
                uint32_t b0, b1, b2, b3, b4, b5, b6, b7;
                ldsm4(b0, b1, b2, b3, bSp + bOff1 + colB);
                ldsm4(b4, b5, b6, b7, bSp + bOff2 + colB);
                mma_bf16(acc[0], azf[sa][ks][0], azf[sa][ks][1], azf[sa][ks][2], azf[sa][ks][3], b0, b2);
                mma_bf16(acc[1], azf[sa][ks][0], azf[sa][ks][1], azf[sa][ks][2], azf[sa][ks][3], b1, b3);
                mma_bf16(acc[2], azf[sa][ks][0], azf[sa][ks][1], azf[sa][ks][2], azf[sa][ks][3], b4, b6);
                mma_bf16(acc[3], azf[sa][ks][0], azf[sa][ks][1], azf[sa][ks][2], azf[sa][ks][3], b5, b7);
            }
        }

        // ---- epilogue: approx d, top-2 per lane (identical to R12) ----
        {
            const float* cbn = (const float*)(smem + buf * BSTRIDE + 65536);
            int cloc = 32 * half + (lane & 3) * 2;
            #pragma unroll
            for (int f = 0; f < 4; f++) {
                float cnx = cbn[cloc + f * 8];
                float cny = cbn[cloc + f * 8 + 1];
                int col = t * PANEL + cloc + f * 8;
                float d;
                d = __fmaf_rn(-2.f, acc[f][0], __fadd_rn(ZA, cnx));
                UPD(d, col, dA1, kA1, dA2, kA2);
                d = __fmaf_rn(-2.f, acc[f][1], __fadd_rn(ZA, cny));
                UPD(d, col + 1, dA1, kA1, dA2, kA2);
                d = __fmaf_rn(-2.f, acc[f][2], __fadd_rn(ZB, cnx));
                UPD(d, col, dB1, kB1, dB2, kB2);
                d = __fmaf_rn(-2.f, acc[f][3], __fadd_rn(ZB, cny));
                UPD(d, col + 1, dB1, kB1, dB2, kB2);
                acc[f][0] = acc[f][1] = acc[f][2] = acc[f][3] = 0.f;
            }
        }
    }

    // ---- write candidates: 16 per row ----
    {
        int baseA = (n0 + rA) * 16 + half * 8 + (lane & 3) * 2;
        g_cand[baseA]     = kA1;
        g_cand[baseA + 1] = kA2;
        int baseB = (n0 + rA + 8) * 16 + half * 8 + (lane & 3) * 2;
        g_cand[baseB]     = kB1;
        g_cand[baseB + 1] = kB2;
    }
}

// ---------------- K3b: exact fp32 refinement (R2-proven semantics) --------
__global__ void __launch_bounds__(256, 2)
k_refine(const float* __restrict__ z, const float* __restrict__ cb) {
    __shared__ float zs[16][256];
    int tid = threadIdx.x;
    int n0 = blockIdx.x * 16;
    int b = n0 >> 12, p0 = n0 & 4095;

    for (int i = tid; i < 16 * 256; i += 256) {
        int c = i >> 4, pr = i & 15;
        zs[pr][c] = z[((size_t)b * CDIM + c) * SPAT + p0 + pr];
    }
    __syncthreads();

    int r = tid >> 4;
    int ci = tid & 15;
    int n = n0 + r;
    int k = g_cand[n * 16 + ci];

    const float4* cbr = (const float4*)(cb + (size_t)k * CDIM);
    const float4* zr = (const float4*)zs[r];
    float acc = 0.f;
    #pragma unroll 8
    for (int c4 = 0; c4 < 64; c4++) {
        float4 bv = cbr[c4];
        float4 av = zr[c4];
        acc = fmaf(av.x, bv.x, acc);
        acc = fmaf(av.y, bv.y, acc);
        acc = fmaf(av.z, bv.z, acc);
        acc = fmaf(av.w, bv.w, acc);
    }
    float t1 = __fadd_rn(g_zn[n], g_cbn[k]);
    float d = __fmaf_rn(-2.f, acc, t1);

    #pragma unroll
    for (int o = 8; o > 0; o >>= 1) {
        float od = __shfl_xor_sync(~0u, d, o, 16);
        int   ok = __shfl_xor_sync(~0u, k, o, 16);
        if (od < d || (od == d && ok < k)) { d = od; k = ok; }
    }
    if (ci == 0) g_idx[n] = k;
}

// ---------------- K4: gather output + loss ----------------
__global__ void k_out(const float* __restrict__ z, const float* __restrict__ cb,
                      float* __restrict__ out, int out_size) {
    int n = blockIdx.x * 256 + threadIdx.x;
    int b = n >> 12, p = n & 4095;
    int myk = g_idx[n];
    const float* crow = cb + (size_t)myk * CDIM;
    const float* zp = z + (size_t)b * CDIM * SPAT + p;
    float* op = out + (size_t)b * CDIM * SPAT + p;
    double ls = 0.0;
    #pragma unroll 4
    for (int c = 0; c < CDIM; c++) {
        float q = crow[c];
        float zv = zp[(size_t)c * SPAT];
        op[(size_t)c * SPAT] = q;
        float dlt = q - zv;
        ls += (double)dlt * (double)dlt;
    }
    #pragma unroll
    for (int o = 16; o > 0; o >>= 1) ls += __shfl_xor_sync(~0u, ls, o);
    __shared__ double ws[8];
    if ((threadIdx.x & 31) == 0) ws[threadIdx.x >> 5] = ls;
    __syncthreads();
    if (threadIdx.x == 0) {
        double t = 0.0;
        #pragma unroll
        for (int i = 0; i < 8; i++) t += ws[i];
        atomicAdd(&g_loss, t);
    }
    if (out_size >= OUT_ELEMS + 1 + NROWS)
        out[OUT_ELEMS + 1 + n] = (float)myk;
}

__global__ void k_fin(float* __restrict__ out, int out_size) {
    if (out_size >= OUT_ELEMS + 1)
        out[OUT_ELEMS] = (float)((2.0 * g_loss) / (double)OUT_ELEMS);
}

extern "C" void kernel_launch(void* const* d_in, const int* in_sizes, int n_in,
                              void* d_out, int out_size) {
    const float* z  = (const float*)d_in[0];
    const float* cb = (const float*)d_in[1];
    if (n_in >= 2 && in_sizes[0] == K_CODES * CDIM) {
        z  = (const float*)d_in[1];
        cb = (const float*)d_in[0];
    }
    float* out = (float*)d_out;

    cudaFuncSetAttribute(k_argmin, cudaFuncAttributeMaxDynamicSharedMemorySize, SMEM_TOTAL);

    k_cbprep<<<K_CODES, 256>>>(cb);
    k_pack<<<T_TILES, 256>>>();
    k_zn<<<NROWS / 256, 256>>>(z);
    k_zero<<<1, 1>>>();
    k_argmin<<<NROWS / ROWS_CTA, 256, SMEM_TOTAL>>>(z);
    k_refine<<<NROWS / 16, 256>>>(z, cb);
    k_out<<<NROWS / 256, 256>>>(z, cb, out, out_size);
    k_fin<<<1, 1>>>(out, out_size);
}